// round 15
// baseline (speedup 1.0000x reference)
#include <cuda_runtime.h>
#include <cuda_fp16.h>
#include <cstdint>
#include <math.h>

#define BATCH 32768
#define NA 9
#define NR 4
#define LRS 0.2f
#define BN_EPS 1e-5f
#define MTOT (BATCH*NA)

// ---- scratch (device globals; no allocs) ----
__device__ __align__(16) __half g_h0[(size_t)MTOT*64];
__device__ __align__(16) __half g_h1[(size_t)MTOT*128];
__device__ __align__(16) __half g_h2[(size_t)MTOT*256];
__device__ __align__(16) __half g_x [(size_t)MTOT*640];
__device__ __align__(16) __half g_wt[206848];
__device__ float g_stats[3][2][16];

// ---------------- helpers ----------------
static __device__ __forceinline__ uint32_t s2u(const void* p){
    uint32_t a;
    asm("{ .reg .u64 t; cvta.to.shared.u64 t, %1; cvt.u32.u64 %0, t; }":"=r"(a):"l"(p));
    return a;
}
#define CPA16(dst,src) asm volatile("cp.async.cg.shared.global [%0], [%1], 16;"::"r"(dst),"l"(src):"memory")
#define CPA_COMMIT()   asm volatile("cp.async.commit_group;":::"memory")
#define CPA_WAIT(n)    asm volatile("cp.async.wait_group %0;"::"n"(n):"memory")

static __device__ __forceinline__ void mma_f16(
    float& d0, float& d1, float& d2, float& d3,
    uint32_t a0, uint32_t a1, uint32_t a2, uint32_t a3,
    uint32_t b0, uint32_t b1)
{
    asm volatile(
        "mma.sync.aligned.m16n8k16.row.col.f32.f16.f16.f32 "
        "{%0,%1,%2,%3}, {%4,%5,%6,%7}, {%8,%9}, {%0,%1,%2,%3};"
        : "+f"(d0), "+f"(d1), "+f"(d2), "+f"(d3)
        : "r"(a0), "r"(a1), "r"(a2), "r"(a3), "r"(b0), "r"(b1));
}

// ---------------- weight pack (k16 fp16 fragment layout) ----------------
template<int DIN,int DOUT,int K5P>
static __device__ __forceinline__ void wt_pack(
    const float* ws, const float* wr, __half* bp, int i)
{
    int n = i / K5P, k = i - n*K5P;
    float v = 0.f;
    if (k < DIN) v = ws[k*DOUT + n];
    else if (k < 5*DIN) {
        int r = (k - DIN) / DIN, kk = (k - DIN) - r*DIN;
        v = wr[(size_t)(r*DIN + kk)*DOUT + n];
    }
    int l = (n & 7)*4 + ((k & 7) >> 1);
    int rg = (k >> 3) & 1, hb = k & 1;
    bp[((size_t)(n >> 3)*(K5P/16) + (k >> 4))*128 + l*4 + rg*2 + hb] = __float2half_rn(v);
}

__global__ void prep_kernel(const float* ws0, const float* wr0,
                            const float* ws1, const float* wr1,
                            const float* ws2, const float* wr2,
                            __half* wt)
{
    int idx = blockIdx.x*256 + threadIdx.x;
    if (blockIdx.x == 0 && threadIdx.x < 96) ((float*)g_stats)[threadIdx.x] = 0.f;
    if (idx < 2048)             wt_pack<5,64,32>    (ws0, wr0, wt,          idx);
    else if (idx < 43008)       wt_pack<64,128,320> (ws1, wr1, wt + 2048,   idx - 2048);
    else if (idx < 206848)      wt_pack<128,256,640>(ws2, wr2, wt + 43008,  idx - 43008);
}

// ---------------- X build, block0 only (fp32 atom feats, no norm) ----------------
__global__ void __launch_bounds__(256) x_build0(
    const float* __restrict__ hin, const float* __restrict__ adj,
    __half* __restrict__ Xo)
{
    constexpr int DIN = 5, K5P = 32, MB = 8;
    __shared__ float h_s[MB*NA*DIN];
    __shared__ float adj_s[MB*NR*NA*NA];
    const int tid = threadIdx.x;
    const size_t mb = (size_t)blockIdx.x * MB;
    for (int i = tid; i < MB*NA*DIN; i += 256)
        h_s[i] = hin[mb*NA*DIN + i];
    for (int i = tid; i < MB*NR*NA*NA; i += 256)
        adj_s[i] = adj[mb*NR*NA*NA + i];
    __syncthreads();
    for (int i = tid; i < MB*NA*(K5P/2); i += 256){
        int row = i / (K5P/2), pp = i - row*(K5P/2);
        int m = row / NA, n = row - m*NA;
        float vv[2];
        #pragma unroll
        for (int t = 0; t < 2; t++){
            int col = pp*2 + t;
            float v = 0.f;
            if (col < DIN) v = h_s[row*DIN + col];
            else if (col < 5*DIN){
                int r = (col - DIN) / DIN, d = (col - DIN) - r*DIN;
                const float* ar = &adj_s[((m*NR + r)*NA + n)*NA];
                const float* hc = &h_s[m*NA*DIN + d];
                #pragma unroll
                for (int mm = 0; mm < NA; mm++) v = fmaf(ar[mm], hc[mm*DIN], v);
            }
            vv[t] = v;
        }
        *(__half2*)&Xo[mb*NA*K5P + (size_t)row*K5P + pp*2] = __floats2half2_rn(vv[0], vv[1]);
    }
}

// ---------------- X build (register-blocked, fp16 h_s, relation-paired) ------------
// task = (batch, r-pair, 3-row n-tile, 8-col group) -> acc[2][3][8]
template<int DIN, int SIN>
__global__ void __launch_bounds__(256,4) x_build_s(
    const __half* __restrict__ hin,   // [B,9,DIN]
    const float* __restrict__ adj,    // [B,4,9,9]
    const float* __restrict__ gamma, const float* __restrict__ beta,
    __half* __restrict__ Xo,          // [B*9, 5*DIN]
    float invp)
{
    constexpr int K5P = 5*DIN;
    constexpr int MB  = 8;
    constexpr int NCG = DIN/8;
    __shared__ __align__(16) __half h_s[MB*NA*DIN];
    __shared__ float adj_s[MB*NR*81];
    __shared__ float nrm[32];
    const int tid = threadIdx.x;
    const size_t mb = (size_t)blockIdx.x * MB;
    if (tid < NA){
        float s = g_stats[SIN][0][tid], q = g_stats[SIN][1][tid];
        float mean = s*invp, var = q*invp - mean*mean;
        float a = rsqrtf(var + BN_EPS) * gamma[tid];
        nrm[tid] = a; nrm[16+tid] = beta[tid] - mean*a;
    }
    __syncthreads();

    // phase A: load h (int4), normalize+act, store h_s fp16 AND X[:,0:DIN] fp16
    const int4* hv = (const int4*)(hin + mb*NA*DIN);
    for (int i = tid; i < MB*NA*DIN/8; i += 256){
        int4 raw = hv[i];
        __half2 hh[4];
        *(int*)&hh[0] = raw.x; *(int*)&hh[1] = raw.y;
        *(int*)&hh[2] = raw.z; *(int*)&hh[3] = raw.w;
        int idx0 = i*8;
        int row = idx0 / DIN;
        int n = row % NA;
        float a = nrm[n], c = nrm[16+n];
        __half2 pk[4];
        #pragma unroll
        for (int q = 0; q < 4; q++){
            float2 f = __half22float2(hh[q]);
            float v0 = fmaf(f.x, a, c); v0 = v0 > 0.f ? v0 : LRS*v0;
            float v1 = fmaf(f.y, a, c); v1 = v1 > 0.f ? v1 : LRS*v1;
            pk[q] = __floats2half2_rn(v0, v1);
        }
        int4 st;
        st.x = *(int*)&pk[0]; st.y = *(int*)&pk[1];
        st.z = *(int*)&pk[2]; st.w = *(int*)&pk[3];
        *(int4*)&h_s[idx0] = st;
        int col0 = idx0 - row*DIN;
        *(int4*)&Xo[(mb*NA + row)*K5P + col0] = st;
    }
    for (int i = tid; i < MB*NR*81; i += 256)
        adj_s[i] = adj[mb*NR*81 + i];
    __syncthreads();

    // phase B: task = (b, rp, nt, cg); 2 relations x 3 rows x 8 cols; fp32 accum
    for (int t = tid; t < MB*2*3*NCG; t += 256){
        int cg = t % NCG, t2 = t / NCG;
        int nt = t2 % 3, brp = t2 / 3;
        int rp = brp & 1, b = brp >> 1;
        const float* arow0 = &adj_s[(b*NR + rp*2)*81 + nt*3*9];
        const float* arow1 = arow0 + 81;
        const __half* hb  = &h_s[b*NA*DIN + cg*8];
        float acc[2][3][8];
        #pragma unroll
        for (int rr = 0; rr < 2; rr++)
            #pragma unroll
            for (int nn = 0; nn < 3; nn++)
                #pragma unroll
                for (int j = 0; j < 8; j++) acc[rr][nn][j] = 0.f;
        #pragma unroll
        for (int m = 0; m < 9; m++){
            int4 raw = *(const int4*)&hb[m*DIN];
            __half2 hh[4];
            *(int*)&hh[0] = raw.x; *(int*)&hh[1] = raw.y;
            *(int*)&hh[2] = raw.z; *(int*)&hh[3] = raw.w;
            float h8[8];
            #pragma unroll
            for (int q = 0; q < 4; q++){
                float2 f = __half22float2(hh[q]);
                h8[2*q] = f.x; h8[2*q+1] = f.y;
            }
            #pragma unroll
            for (int nn = 0; nn < 3; nn++){
                float a0 = arow0[nn*9 + m];
                float a1 = arow1[nn*9 + m];
                #pragma unroll
                for (int j = 0; j < 8; j++){
                    acc[0][nn][j] = fmaf(a0, h8[j], acc[0][nn][j]);
                    acc[1][nn][j] = fmaf(a1, h8[j], acc[1][nn][j]);
                }
            }
        }
        #pragma unroll
        for (int rr = 0; rr < 2; rr++){
            int r = rp*2 + rr;
            size_t xb0 = (mb + b)*NA*K5P + (size_t)(nt*3)*K5P + DIN + r*DIN + cg*8;
            #pragma unroll
            for (int nn = 0; nn < 3; nn++){
                __half2 p0 = __floats2half2_rn(acc[rr][nn][0], acc[rr][nn][1]);
                __half2 p1 = __floats2half2_rn(acc[rr][nn][2], acc[rr][nn][3]);
                __half2 p2 = __floats2half2_rn(acc[rr][nn][4], acc[rr][nn][5]);
                __half2 p3 = __floats2half2_rn(acc[rr][nn][6], acc[rr][nn][7]);
                int4 st; st.x = *(int*)&p0; st.y = *(int*)&p1;
                st.z = *(int*)&p2; st.w = *(int*)&p3;
                *(int4*)&Xo[xb0 + (size_t)nn*K5P] = st;
            }
        }
    }
}

// ---------------- fp16 mma.sync GEMM, NSTG-deep cp.async pipeline ----------------
template<int N, int NCH, int K5P, int MROWS, int SOUT, int MINCTA, int NSTG>
__global__ void __launch_bounds__(256, MINCTA) gemm_mma(
    const __half* __restrict__ X,
    const __half* __restrict__ Bp,
    const float* __restrict__ bias,
    __half* __restrict__ hout)
{
    constexpr int MT_W = MROWS/64;
    constexpr int NT   = N/16;
    constexpr int ASTR = 40;
    constexpr int ASZ  = MROWS*ASTR;
    constexpr int BSZ  = N*32;
    extern __shared__ __align__(16) __half smh[];
    __half* As = smh;                 // [NSTG][ASZ]
    __half* Bs = smh + NSTG*ASZ;      // [NSTG][BSZ]
    __shared__ float red[32];
    __shared__ float bias_s[N];

    const int tid = threadIdx.x, lane = tid & 31, wid = tid >> 5;
    const int warp_n = wid & 1, warp_m = wid >> 1;
    const int mBase = blockIdx.x * MROWS;

    if (tid < 32) red[tid] = 0.f;
    for (int i = tid; i < N; i += 256) bias_s[i] = bias[i];

    auto loadA = [&](int kc, int s){
        const __half* src = X + (size_t)mBase*K5P + kc*32;
        #pragma unroll
        for (int i = tid; i < MROWS*4; i += 256){
            int row = i >> 2, seg = i & 3;
            CPA16(s2u(As + s*ASZ + row*ASTR + seg*8), src + (size_t)row*K5P + seg*8);
        }
    };
    auto loadB = [&](int kc, int s){
        #pragma unroll
        for (int i = tid; i < N*4; i += 256){
            int n8 = i >> 5, rem = i & 31, ks = rem >> 4, q = rem & 15;
            const __half* src = Bp + ((size_t)n8*(K5P/16) + kc*2 + ks)*128 + q*8;
            CPA16(s2u(Bs + s*BSZ + (n8*2 + ks)*128 + q*8), src);
        }
    };

    // prologue: NSTG-1 uniform commits
    #pragma unroll
    for (int s = 0; s < NSTG-1; s++){
        if (s < NCH){ loadA(s, s); loadB(s, s); }
        CPA_COMMIT();
    }

    float cacc[MT_W][NT][4];
    #pragma unroll
    for (int mtw=0; mtw<MT_W; mtw++)
        #pragma unroll
        for (int j=0;j<NT;j++)
            #pragma unroll
            for (int q=0;q<4;q++) cacc[mtw][j][q] = 0.f;

    for (int kc = 0; kc < NCH; kc++){
        CPA_WAIT(NSTG-2);               // chunk kc resident
        __syncthreads();                // all warps past compute(kc-1); data visible
        {
            int ld = kc + NSTG - 1;     // refill slot (kc-1)%NSTG
            if (ld < NCH){ loadA(ld, ld % NSTG); loadB(ld, ld % NSTG); }
            CPA_COMMIT();
        }
        const int s = kc % NSTG;
        const uint32_t* Au = (const uint32_t*)(As + s*ASZ);
        const uint32_t* Bu = (const uint32_t*)(Bs + s*BSZ);
        #pragma unroll
        for (int ks = 0; ks < 2; ks++){
            uint32_t a[MT_W][4];
            #pragma unroll
            for (int mtw = 0; mtw < MT_W; mtw++){
                int r0 = (warp_m*MT_W + mtw)*16 + (lane >> 2);
                int kw = ks*8 + (lane & 3);
                a[mtw][0] = Au[r0*20 + kw];
                a[mtw][1] = Au[(r0+8)*20 + kw];
                a[mtw][2] = Au[r0*20 + kw + 4];
                a[mtw][3] = Au[(r0+8)*20 + kw + 4];
            }
            #pragma unroll
            for (int j = 0; j < NT; j++){
                int n8 = warp_n*NT + j;
                uint32_t b0 = Bu[(n8*2 + ks)*64 + lane*2];
                uint32_t b1 = Bu[(n8*2 + ks)*64 + lane*2 + 1];
                #pragma unroll
                for (int mtw = 0; mtw < MT_W; mtw++)
                    mma_f16(cacc[mtw][j][0], cacc[mtw][j][1],
                            cacc[mtw][j][2], cacc[mtw][j][3],
                            a[mtw][0], a[mtw][1], a[mtw][2], a[mtw][3],
                            b0, b1);
            }
        }
    }

    // epilogue: bias, fp16 store, BN stats
    #pragma unroll
    for (int mtw = 0; mtw < MT_W; mtw++){
        #pragma unroll
        for (int half = 0; half < 2; half++){
            int r0   = (warp_m*MT_W + mtw)*16 + (lane >> 2) + half*8;
            int grow = mBase + r0;
            int an   = grow % NA;
            float ssum = 0.f, qsum = 0.f;
            __half* op = &hout[(size_t)grow*N];
            #pragma unroll
            for (int j = 0; j < NT; j++){
                int col = warp_n*(N/2) + j*8 + (lane & 3)*2;
                float v0 = cacc[mtw][j][half*2+0] + bias_s[col];
                float v1 = cacc[mtw][j][half*2+1] + bias_s[col+1];
                *(__half2*)(op + col) = __floats2half2_rn(v0, v1);
                ssum += v0 + v1;
                qsum = fmaf(v0, v0, qsum); qsum = fmaf(v1, v1, qsum);
            }
            atomicAdd(&red[an],      ssum);
            atomicAdd(&red[16 + an], qsum);
        }
    }
    __syncthreads();
    if (tid < NA){
        atomicAdd(&g_stats[SOUT][0][tid], red[tid]);
        atomicAdd(&g_stats[SOUT][1][tid], red[16 + tid]);
    }
}

// ---------------- readout: BN + act + masked sum + FC (int4 loads) ------------
__global__ void __launch_bounds__(256) readout_kernel(
    const float* __restrict__ mask, const float* __restrict__ fcw,
    const float* __restrict__ fcb,  const float* __restrict__ gamma,
    const float* __restrict__ beta, float* __restrict__ out, float inv_count)
{
    __shared__ float a_s[NA], c_s[NA], fcs[256];
    int tid = threadIdx.x;
    if (tid < NA){
        float s = g_stats[2][0][tid], q = g_stats[2][1][tid];
        float mean = s*inv_count, var = q*inv_count - mean*mean;
        float a = rsqrtf(var + BN_EPS)*gamma[tid];
        a_s[tid] = a; c_s[tid] = beta[tid] - mean*a;
    }
    fcs[tid] = fcw[tid];
    __syncthreads();
    int lane = tid & 31, w = tid >> 5;
    int b = blockIdx.x*8 + w;
    int e0 = lane*8;
    float accv = 0.f;
    #pragma unroll
    for (int n = 0; n < NA; n++){
        float mk = mask[b*NA + n];
        const int4* hp = (const int4*)(g_h2 + ((size_t)b*NA + n)*256);
        int4 raw = hp[lane];
        float aa = a_s[n], cc = c_s[n];
        __half2 hh[4];
        *(int*)&hh[0] = raw.x; *(int*)&hh[1] = raw.y;
        *(int*)&hh[2] = raw.z; *(int*)&hh[3] = raw.w;
        #pragma unroll
        for (int q = 0; q < 4; q++){
            float2 f = __half22float2(hh[q]);
            float v0 = fmaf(f.x, aa, cc); v0 = v0 > 0.f ? v0 : LRS*v0;
            float v1 = fmaf(f.y, aa, cc); v1 = v1 > 0.f ? v1 : LRS*v1;
            accv = fmaf(v0*mk, fcs[e0 + 2*q],     accv);
            accv = fmaf(v1*mk, fcs[e0 + 2*q + 1], accv);
        }
    }
    #pragma unroll
    for (int o = 16; o > 0; o >>= 1) accv += __shfl_xor_sync(0xffffffffu, accv, o);
    if (lane == 0) out[b] = accv + fcb[0];
}

extern "C" void kernel_launch(void* const* d_in, const int* in_sizes, int n_in,
                              void* d_out, int out_size)
{
    const float* atom = (const float*)d_in[0];
    const float* adj  = (const float*)d_in[1];
    const float* mask = (const float*)d_in[2];
    const float* ws0=(const float*)d_in[3],  *wr0=(const float*)d_in[4],  *b0=(const float*)d_in[5],  *g0=(const float*)d_in[6],  *be0=(const float*)d_in[7];
    const float* ws1=(const float*)d_in[8],  *wr1=(const float*)d_in[9],  *b1=(const float*)d_in[10], *g1=(const float*)d_in[11], *be1=(const float*)d_in[12];
    const float* ws2=(const float*)d_in[13], *wr2=(const float*)d_in[14], *b2=(const float*)d_in[15], *g2=(const float*)d_in[16], *be2=(const float*)d_in[17];
    const float* fcw=(const float*)d_in[18], *fcb=(const float*)d_in[19];
    float* out = (float*)d_out;

    __half *h0,*h1,*h2,*xb,*wtb;
    cudaGetSymbolAddress((void**)&h0, g_h0);
    cudaGetSymbolAddress((void**)&h1, g_h1);
    cudaGetSymbolAddress((void**)&h2, g_h2);
    cudaGetSymbolAddress((void**)&xb, g_x);
    cudaGetSymbolAddress((void**)&wtb, g_wt);

    // dynamic smem: NSTG*(MROWS*40 + N*32) halves * 2 bytes
    const int sm0 = 2*(128*40 + 64*32)  * 2;   //  28672
    const int sm1 = 6*(128*40 + 128*32) * 2;   // 110592
    const int sm2 = 5*(64*40  + 256*32) * 2;   // 107520
    cudaFuncSetAttribute((const void*)gemm_mma<64,1,32,128,0,3,2>,
                         cudaFuncAttributeMaxDynamicSharedMemorySize, sm0);
    cudaFuncSetAttribute((const void*)gemm_mma<128,10,320,128,1,2,6>,
                         cudaFuncAttributeMaxDynamicSharedMemorySize, sm1);
    cudaFuncSetAttribute((const void*)gemm_mma<256,20,640,64,2,2,5>,
                         cudaFuncAttributeMaxDynamicSharedMemorySize, sm2);

    prep_kernel<<<808,256>>>(ws0, wr0, ws1, wr1, ws2, wr2, wtb);

    // block 0
    x_build0<<<BATCH/8,256>>>(atom, adj, xb);
    gemm_mma<64,1,32,128,0,3,2><<<MTOT/128,256,sm0>>>(xb, wtb, b0, h0);

    // block 1
    x_build_s<64,0><<<BATCH/8,256>>>(h0, adj, g0, be0, xb, 1.f/((float)BATCH*64.f));
    gemm_mma<128,10,320,128,1,2,6><<<MTOT/128,256,sm1>>>(xb, wtb + 2048, b1, h1);

    // block 2
    x_build_s<128,1><<<BATCH/8,256>>>(h1, adj, g1, be1, xb, 1.f/((float)BATCH*128.f));
    gemm_mma<256,20,640,64,2,2,5><<<MTOT/64,256,sm2>>>(xb, wtb + 43008, b2, h2);

    readout_kernel<<<BATCH/8,256>>>(mask, fcw, fcb, g2, be2, out,
                                    1.f/((float)BATCH*256.f));
}

// round 16
// speedup vs baseline: 1.0275x; 1.0275x over previous
#include <cuda_runtime.h>
#include <cuda_fp16.h>
#include <cstdint>
#include <math.h>

#define BATCH 32768
#define NA 9
#define NR 4
#define LRS 0.2f
#define BN_EPS 1e-5f
#define MTOT (BATCH*NA)

// ---- scratch (device globals; no allocs) ----
__device__ __align__(16) __half g_h0[(size_t)MTOT*64];
__device__ __align__(16) __half g_h1[(size_t)MTOT*128];
__device__ __align__(16) __half g_h2[(size_t)MTOT*256];
__device__ __align__(16) __half g_x [(size_t)MTOT*640];
__device__ __align__(16) __half g_wt[206848];
__device__ float g_stats[3][2][16];

// ---------------- helpers ----------------
static __device__ __forceinline__ uint32_t s2u(const void* p){
    uint32_t a;
    asm("{ .reg .u64 t; cvta.to.shared.u64 t, %1; cvt.u32.u64 %0, t; }":"=r"(a):"l"(p));
    return a;
}
#define CPA16(dst,src) asm volatile("cp.async.cg.shared.global [%0], [%1], 16;"::"r"(dst),"l"(src):"memory")
#define CPA_COMMIT()   asm volatile("cp.async.commit_group;":::"memory")
#define CPA_WAIT(n)    asm volatile("cp.async.wait_group %0;"::"n"(n):"memory")

static __device__ __forceinline__ void stcs16(void* p, int4 v){
    asm volatile("st.global.cs.v4.b32 [%0], {%1,%2,%3,%4};"
        :: "l"(p), "r"(v.x), "r"(v.y), "r"(v.z), "r"(v.w) : "memory");
}

static __device__ __forceinline__ void mma_f16(
    float& d0, float& d1, float& d2, float& d3,
    uint32_t a0, uint32_t a1, uint32_t a2, uint32_t a3,
    uint32_t b0, uint32_t b1)
{
    asm volatile(
        "mma.sync.aligned.m16n8k16.row.col.f32.f16.f16.f32 "
        "{%0,%1,%2,%3}, {%4,%5,%6,%7}, {%8,%9}, {%0,%1,%2,%3};"
        : "+f"(d0), "+f"(d1), "+f"(d2), "+f"(d3)
        : "r"(a0), "r"(a1), "r"(a2), "r"(a3), "r"(b0), "r"(b1));
}

// ---------------- weight pack (k16 fp16 fragment layout) ----------------
template<int DIN,int DOUT,int K5P>
static __device__ __forceinline__ void wt_pack(
    const float* ws, const float* wr, __half* bp, int i)
{
    int n = i / K5P, k = i - n*K5P;
    float v = 0.f;
    if (k < DIN) v = ws[k*DOUT + n];
    else if (k < 5*DIN) {
        int r = (k - DIN) / DIN, kk = (k - DIN) - r*DIN;
        v = wr[(size_t)(r*DIN + kk)*DOUT + n];
    }
    int l = (n & 7)*4 + ((k & 7) >> 1);
    int rg = (k >> 3) & 1, hb = k & 1;
    bp[((size_t)(n >> 3)*(K5P/16) + (k >> 4))*128 + l*4 + rg*2 + hb] = __float2half_rn(v);
}

__global__ void prep_kernel(const float* ws0, const float* wr0,
                            const float* ws1, const float* wr1,
                            const float* ws2, const float* wr2,
                            __half* wt)
{
    int idx = blockIdx.x*256 + threadIdx.x;
    if (blockIdx.x == 0 && threadIdx.x < 96) ((float*)g_stats)[threadIdx.x] = 0.f;
    if (idx < 2048)             wt_pack<5,64,32>    (ws0, wr0, wt,          idx);
    else if (idx < 43008)       wt_pack<64,128,320> (ws1, wr1, wt + 2048,   idx - 2048);
    else if (idx < 206848)      wt_pack<128,256,640>(ws2, wr2, wt + 43008,  idx - 43008);
}

// ---------------- X build, block0 only (fp32 atom feats, no norm) ----------------
__global__ void __launch_bounds__(256) x_build0(
    const float* __restrict__ hin, const float* __restrict__ adj,
    __half* __restrict__ Xo)
{
    constexpr int DIN = 5, K5P = 32, MB = 8;
    __shared__ float h_s[MB*NA*DIN];
    __shared__ float adj_s[MB*NR*NA*NA];
    const int tid = threadIdx.x;
    const size_t mb = (size_t)blockIdx.x * MB;
    for (int i = tid; i < MB*NA*DIN; i += 256)
        h_s[i] = hin[mb*NA*DIN + i];
    for (int i = tid; i < MB*NR*NA*NA; i += 256)
        adj_s[i] = adj[mb*NR*NA*NA + i];
    __syncthreads();
    for (int i = tid; i < MB*NA*(K5P/2); i += 256){
        int row = i / (K5P/2), pp = i - row*(K5P/2);
        int m = row / NA, n = row - m*NA;
        float vv[2];
        #pragma unroll
        for (int t = 0; t < 2; t++){
            int col = pp*2 + t;
            float v = 0.f;
            if (col < DIN) v = h_s[row*DIN + col];
            else if (col < 5*DIN){
                int r = (col - DIN) / DIN, d = (col - DIN) - r*DIN;
                const float* ar = &adj_s[((m*NR + r)*NA + n)*NA];
                const float* hc = &h_s[m*NA*DIN + d];
                #pragma unroll
                for (int mm = 0; mm < NA; mm++) v = fmaf(ar[mm], hc[mm*DIN], v);
            }
            vv[t] = v;
        }
        *(__half2*)&Xo[mb*NA*K5P + (size_t)row*K5P + pp*2] = __floats2half2_rn(vv[0], vv[1]);
    }
}

// ---------------- X build (register-blocked, fp16 h_s, streaming X stores) --------
// task = (batch, relation, 3-row n-tile, 8-col group) -> acc[3][8]
template<int DIN, int SIN>
__global__ void __launch_bounds__(256,4) x_build_s(
    const __half* __restrict__ hin,   // [B,9,DIN]
    const float* __restrict__ adj,    // [B,4,9,9]
    const float* __restrict__ gamma, const float* __restrict__ beta,
    __half* __restrict__ Xo,          // [B*9, 5*DIN]
    float invp)
{
    constexpr int K5P = 5*DIN;
    constexpr int MB  = 8;
    constexpr int NCG = DIN/8;
    __shared__ __align__(16) __half h_s[MB*NA*DIN];   // fp16
    __shared__ float adj_s[MB*NR*81];
    __shared__ float nrm[32];
    const int tid = threadIdx.x;
    const size_t mb = (size_t)blockIdx.x * MB;
    if (tid < NA){
        float s = g_stats[SIN][0][tid], q = g_stats[SIN][1][tid];
        float mean = s*invp, var = q*invp - mean*mean;
        float a = rsqrtf(var + BN_EPS) * gamma[tid];
        nrm[tid] = a; nrm[16+tid] = beta[tid] - mean*a;
    }
    __syncthreads();

    // phase A: load h (int4), normalize+act, store h_s fp16 AND X[:,0:DIN] fp16
    const int4* hv = (const int4*)(hin + mb*NA*DIN);
    for (int i = tid; i < MB*NA*DIN/8; i += 256){
        int4 raw = hv[i];
        __half2 hh[4];
        *(int*)&hh[0] = raw.x; *(int*)&hh[1] = raw.y;
        *(int*)&hh[2] = raw.z; *(int*)&hh[3] = raw.w;
        int idx0 = i*8;
        int row = idx0 / DIN;
        int n = row % NA;
        float a = nrm[n], c = nrm[16+n];
        __half2 pk[4];
        #pragma unroll
        for (int q = 0; q < 4; q++){
            float2 f = __half22float2(hh[q]);
            float v0 = fmaf(f.x, a, c); v0 = v0 > 0.f ? v0 : LRS*v0;
            float v1 = fmaf(f.y, a, c); v1 = v1 > 0.f ? v1 : LRS*v1;
            pk[q] = __floats2half2_rn(v0, v1);
        }
        int4 st;
        st.x = *(int*)&pk[0]; st.y = *(int*)&pk[1];
        st.z = *(int*)&pk[2]; st.w = *(int*)&pk[3];
        *(int4*)&h_s[idx0] = st;
        int col0 = idx0 - row*DIN;
        stcs16(&Xo[(mb*NA + row)*K5P + col0], st);
    }
    for (int i = tid; i < MB*NR*81; i += 256)
        adj_s[i] = adj[mb*NR*81 + i];
    __syncthreads();

    // phase B: task = (b, r, nt, cg); 3 output rows x 8 cols each; fp32 accum
    for (int t = tid; t < MB*NR*3*NCG; t += 256){
        int cg = t % NCG, t2 = t / NCG;
        int nt = t2 % 3, br = t2 / 3;
        int r = br % NR, b = br / NR;
        const float* arow = &adj_s[(b*NR + r)*81 + nt*3*9];
        const __half* hb  = &h_s[b*NA*DIN + cg*8];
        float acc[3][8];
        #pragma unroll
        for (int nn = 0; nn < 3; nn++)
            #pragma unroll
            for (int j = 0; j < 8; j++) acc[nn][j] = 0.f;
        #pragma unroll
        for (int m = 0; m < 9; m++){
            int4 raw = *(const int4*)&hb[m*DIN];
            __half2 hh[4];
            *(int*)&hh[0] = raw.x; *(int*)&hh[1] = raw.y;
            *(int*)&hh[2] = raw.z; *(int*)&hh[3] = raw.w;
            float h8[8];
            #pragma unroll
            for (int q = 0; q < 4; q++){
                float2 f = __half22float2(hh[q]);
                h8[2*q] = f.x; h8[2*q+1] = f.y;
            }
            #pragma unroll
            for (int nn = 0; nn < 3; nn++){
                float a = arow[nn*9 + m];
                #pragma unroll
                for (int j = 0; j < 8; j++) acc[nn][j] = fmaf(a, h8[j], acc[nn][j]);
            }
        }
        size_t xb0 = (mb + b)*NA*K5P + (size_t)(nt*3)*K5P + DIN + r*DIN + cg*8;
        #pragma unroll
        for (int nn = 0; nn < 3; nn++){
            __half2 p0 = __floats2half2_rn(acc[nn][0], acc[nn][1]);
            __half2 p1 = __floats2half2_rn(acc[nn][2], acc[nn][3]);
            __half2 p2 = __floats2half2_rn(acc[nn][4], acc[nn][5]);
            __half2 p3 = __floats2half2_rn(acc[nn][6], acc[nn][7]);
            int4 st; st.x = *(int*)&p0; st.y = *(int*)&p1;
            st.z = *(int*)&p2; st.w = *(int*)&p3;
            stcs16(&Xo[xb0 + (size_t)nn*K5P], st);
        }
    }
}

// ---------------- fp16 mma.sync GEMM, NSTG-deep cp.async pipeline ----------------
template<int N, int NCH, int K5P, int MROWS, int SOUT, int MINCTA, int NSTG>
__global__ void __launch_bounds__(256, MINCTA) gemm_mma(
    const __half* __restrict__ X,
    const __half* __restrict__ Bp,
    const float* __restrict__ bias,
    __half* __restrict__ hout)
{
    constexpr int MT_W = MROWS/64;
    constexpr int NT   = N/16;
    constexpr int ASTR = 40;
    constexpr int ASZ  = MROWS*ASTR;
    constexpr int BSZ  = N*32;
    extern __shared__ __align__(16) __half smh[];
    __half* As = smh;                 // [NSTG][ASZ]
    __half* Bs = smh + NSTG*ASZ;      // [NSTG][BSZ]
    __shared__ float red[32];
    __shared__ float bias_s[N];

    const int tid = threadIdx.x, lane = tid & 31, wid = tid >> 5;
    const int warp_n = wid & 1, warp_m = wid >> 1;
    const int mBase = blockIdx.x * MROWS;

    if (tid < 32) red[tid] = 0.f;
    for (int i = tid; i < N; i += 256) bias_s[i] = bias[i];

    auto loadA = [&](int kc, int s){
        const __half* src = X + (size_t)mBase*K5P + kc*32;
        #pragma unroll
        for (int i = tid; i < MROWS*4; i += 256){
            int row = i >> 2, seg = i & 3;
            CPA16(s2u(As + s*ASZ + row*ASTR + seg*8), src + (size_t)row*K5P + seg*8);
        }
    };
    auto loadB = [&](int kc, int s){
        #pragma unroll
        for (int i = tid; i < N*4; i += 256){
            int n8 = i >> 5, rem = i & 31, ks = rem >> 4, q = rem & 15;
            const __half* src = Bp + ((size_t)n8*(K5P/16) + kc*2 + ks)*128 + q*8;
            CPA16(s2u(Bs + s*BSZ + (n8*2 + ks)*128 + q*8), src);
        }
    };

    // prologue: NSTG-1 uniform commits
    #pragma unroll
    for (int s = 0; s < NSTG-1; s++){
        if (s < NCH){ loadA(s, s); loadB(s, s); }
        CPA_COMMIT();
    }

    float cacc[MT_W][NT][4];
    #pragma unroll
    for (int mtw=0; mtw<MT_W; mtw++)
        #pragma unroll
        for (int j=0;j<NT;j++)
            #pragma unroll
            for (int q=0;q<4;q++) cacc[mtw][j][q] = 0.f;

    for (int kc = 0; kc < NCH; kc++){
        CPA_WAIT(NSTG-2);               // chunk kc resident
        __syncthreads();                // all warps past compute(kc-1); data visible
        {
            int ld = kc + NSTG - 1;     // refill slot (kc-1)%NSTG
            if (ld < NCH){ loadA(ld, ld % NSTG); loadB(ld, ld % NSTG); }
            CPA_COMMIT();
        }
        const int s = kc % NSTG;
        const uint32_t* Au = (const uint32_t*)(As + s*ASZ);
        const uint32_t* Bu = (const uint32_t*)(Bs + s*BSZ);
        #pragma unroll
        for (int ks = 0; ks < 2; ks++){
            uint32_t a[MT_W][4];
            #pragma unroll
            for (int mtw = 0; mtw < MT_W; mtw++){
                int r0 = (warp_m*MT_W + mtw)*16 + (lane >> 2);
                int kw = ks*8 + (lane & 3);
                a[mtw][0] = Au[r0*20 + kw];
                a[mtw][1] = Au[(r0+8)*20 + kw];
                a[mtw][2] = Au[r0*20 + kw + 4];
                a[mtw][3] = Au[(r0+8)*20 + kw + 4];
            }
            #pragma unroll
            for (int j = 0; j < NT; j++){
                int n8 = warp_n*NT + j;
                uint32_t b0 = Bu[(n8*2 + ks)*64 + lane*2];
                uint32_t b1 = Bu[(n8*2 + ks)*64 + lane*2 + 1];
                #pragma unroll
                for (int mtw = 0; mtw < MT_W; mtw++)
                    mma_f16(cacc[mtw][j][0], cacc[mtw][j][1],
                            cacc[mtw][j][2], cacc[mtw][j][3],
                            a[mtw][0], a[mtw][1], a[mtw][2], a[mtw][3],
                            b0, b1);
            }
        }
    }

    // epilogue: bias, fp16 store, BN stats
    #pragma unroll
    for (int mtw = 0; mtw < MT_W; mtw++){
        #pragma unroll
        for (int half = 0; half < 2; half++){
            int r0   = (warp_m*MT_W + mtw)*16 + (lane >> 2) + half*8;
            int grow = mBase + r0;
            int an   = grow % NA;
            float ssum = 0.f, qsum = 0.f;
            __half* op = &hout[(size_t)grow*N];
            #pragma unroll
            for (int j = 0; j < NT; j++){
                int col = warp_n*(N/2) + j*8 + (lane & 3)*2;
                float v0 = cacc[mtw][j][half*2+0] + bias_s[col];
                float v1 = cacc[mtw][j][half*2+1] + bias_s[col+1];
                *(__half2*)(op + col) = __floats2half2_rn(v0, v1);
                ssum += v0 + v1;
                qsum = fmaf(v0, v0, qsum); qsum = fmaf(v1, v1, qsum);
            }
            atomicAdd(&red[an],      ssum);
            atomicAdd(&red[16 + an], qsum);
        }
    }
    __syncthreads();
    if (tid < NA){
        atomicAdd(&g_stats[SOUT][0][tid], red[tid]);
        atomicAdd(&g_stats[SOUT][1][tid], red[16 + tid]);
    }
}

// ---------------- readout: BN + act + masked sum + FC (int4 loads) ------------
__global__ void __launch_bounds__(256) readout_kernel(
    const float* __restrict__ mask, const float* __restrict__ fcw,
    const float* __restrict__ fcb,  const float* __restrict__ gamma,
    const float* __restrict__ beta, float* __restrict__ out, float inv_count)
{
    __shared__ float a_s[NA], c_s[NA], fcs[256];
    int tid = threadIdx.x;
    if (tid < NA){
        float s = g_stats[2][0][tid], q = g_stats[2][1][tid];
        float mean = s*inv_count, var = q*inv_count - mean*mean;
        float a = rsqrtf(var + BN_EPS)*gamma[tid];
        a_s[tid] = a; c_s[tid] = beta[tid] - mean*a;
    }
    fcs[tid] = fcw[tid];
    __syncthreads();
    int lane = tid & 31, w = tid >> 5;
    int b = blockIdx.x*8 + w;
    int e0 = lane*8;
    float accv = 0.f;
    #pragma unroll
    for (int n = 0; n < NA; n++){
        float mk = mask[b*NA + n];
        const int4* hp = (const int4*)(g_h2 + ((size_t)b*NA + n)*256);
        int4 raw = hp[lane];
        float aa = a_s[n], cc = c_s[n];
        __half2 hh[4];
        *(int*)&hh[0] = raw.x; *(int*)&hh[1] = raw.y;
        *(int*)&hh[2] = raw.z; *(int*)&hh[3] = raw.w;
        #pragma unroll
        for (int q = 0; q < 4; q++){
            float2 f = __half22float2(hh[q]);
            float v0 = fmaf(f.x, aa, cc); v0 = v0 > 0.f ? v0 : LRS*v0;
            float v1 = fmaf(f.y, aa, cc); v1 = v1 > 0.f ? v1 : LRS*v1;
            accv = fmaf(v0*mk, fcs[e0 + 2*q],     accv);
            accv = fmaf(v1*mk, fcs[e0 + 2*q + 1], accv);
        }
    }
    #pragma unroll
    for (int o = 16; o > 0; o >>= 1) accv += __shfl_xor_sync(0xffffffffu, accv, o);
    if (lane == 0) out[b] = accv + fcb[0];
}

extern "C" void kernel_launch(void* const* d_in, const int* in_sizes, int n_in,
                              void* d_out, int out_size)
{
    const float* atom = (const float*)d_in[0];
    const float* adj  = (const float*)d_in[1];
    const float* mask = (const float*)d_in[2];
    const float* ws0=(const float*)d_in[3],  *wr0=(const float*)d_in[4],  *b0=(const float*)d_in[5],  *g0=(const float*)d_in[6],  *be0=(const float*)d_in[7];
    const float* ws1=(const float*)d_in[8],  *wr1=(const float*)d_in[9],  *b1=(const float*)d_in[10], *g1=(const float*)d_in[11], *be1=(const float*)d_in[12];
    const float* ws2=(const float*)d_in[13], *wr2=(const float*)d_in[14], *b2=(const float*)d_in[15], *g2=(const float*)d_in[16], *be2=(const float*)d_in[17];
    const float* fcw=(const float*)d_in[18], *fcb=(const float*)d_in[19];
    float* out = (float*)d_out;

    __half *h0,*h1,*h2,*xb,*wtb;
    cudaGetSymbolAddress((void**)&h0, g_h0);
    cudaGetSymbolAddress((void**)&h1, g_h1);
    cudaGetSymbolAddress((void**)&h2, g_h2);
    cudaGetSymbolAddress((void**)&xb, g_x);
    cudaGetSymbolAddress((void**)&wtb, g_wt);

    // dynamic smem: NSTG*(MROWS*40 + N*32) halves * 2 bytes  (R14 configs)
    const int sm0 = 2*(128*40 + 64*32)  * 2;   //  28672
    const int sm1 = 5*(128*40 + 128*32) * 2;   //  92160
    const int sm2 = 4*(64*40  + 256*32) * 2;   //  86016
    cudaFuncSetAttribute((const void*)gemm_mma<64,1,32,128,0,3,2>,
                         cudaFuncAttributeMaxDynamicSharedMemorySize, sm0);
    cudaFuncSetAttribute((const void*)gemm_mma<128,10,320,128,1,2,5>,
                         cudaFuncAttributeMaxDynamicSharedMemorySize, sm1);
    cudaFuncSetAttribute((const void*)gemm_mma<256,20,640,64,2,2,4>,
                         cudaFuncAttributeMaxDynamicSharedMemorySize, sm2);

    prep_kernel<<<808,256>>>(ws0, wr0, ws1, wr1, ws2, wr2, wtb);

    // block 0
    x_build0<<<BATCH/8,256>>>(atom, adj, xb);
    gemm_mma<64,1,32,128,0,3,2><<<MTOT/128,256,sm0>>>(xb, wtb, b0, h0);

    // block 1
    x_build_s<64,0><<<BATCH/8,256>>>(h0, adj, g0, be0, xb, 1.f/((float)BATCH*64.f));
    gemm_mma<128,10,320,128,1,2,5><<<MTOT/128,256,sm1>>>(xb, wtb + 2048, b1, h1);

    // block 2
    x_build_s<128,1><<<BATCH/8,256>>>(h1, adj, g1, be1, xb, 1.f/((float)BATCH*128.f));
    gemm_mma<256,20,640,64,2,2,4><<<MTOT/64,256,sm2>>>(xb, wtb + 43008, b2, h2);

    readout_kernel<<<BATCH/8,256>>>(mask, fcw, fcb, g2, be2, out,
                                    1.f/((float)BATCH*256.f));
}

// round 17
// speedup vs baseline: 1.0510x; 1.0228x over previous
#include <cuda_runtime.h>
#include <cuda_fp16.h>
#include <cstdint>
#include <math.h>

#define BATCH 32768
#define NA 9
#define NR 4
#define LRS 0.2f
#define BN_EPS 1e-5f
#define MTOT (BATCH*NA)

// ---- scratch (device globals; no allocs) ----
__device__ __align__(16) __half g_h0[(size_t)MTOT*64];
__device__ __align__(16) __half g_h1[(size_t)MTOT*128];
__device__ __align__(16) __half g_h2[(size_t)MTOT*256];
__device__ __align__(16) __half g_x [(size_t)MTOT*640];
__device__ __align__(16) __half g_wt[206848];
__device__ float g_stats[3][2][16];

// ---------------- helpers ----------------
static __device__ __forceinline__ uint32_t s2u(const void* p){
    uint32_t a;
    asm("{ .reg .u64 t; cvta.to.shared.u64 t, %1; cvt.u32.u64 %0, t; }":"=r"(a):"l"(p));
    return a;
}
#define CPA16(dst,src) asm volatile("cp.async.cg.shared.global [%0], [%1], 16;"::"r"(dst),"l"(src):"memory")
#define CPA_COMMIT()   asm volatile("cp.async.commit_group;":::"memory")
#define CPA_WAIT(n)    asm volatile("cp.async.wait_group %0;"::"n"(n):"memory")

static __device__ __forceinline__ void mma_f16(
    float& d0, float& d1, float& d2, float& d3,
    uint32_t a0, uint32_t a1, uint32_t a2, uint32_t a3,
    uint32_t b0, uint32_t b1)
{
    asm volatile(
        "mma.sync.aligned.m16n8k16.row.col.f32.f16.f16.f32 "
        "{%0,%1,%2,%3}, {%4,%5,%6,%7}, {%8,%9}, {%0,%1,%2,%3};"
        : "+f"(d0), "+f"(d1), "+f"(d2), "+f"(d3)
        : "r"(a0), "r"(a1), "r"(a2), "r"(a3), "r"(b0), "r"(b1));
}

// ---------------- weight pack (k16 fp16 fragment layout) ----------------
template<int DIN,int DOUT,int K5P>
static __device__ __forceinline__ void wt_pack(
    const float* ws, const float* wr, __half* bp, int i)
{
    int n = i / K5P, k = i - n*K5P;
    float v = 0.f;
    if (k < DIN) v = ws[k*DOUT + n];
    else if (k < 5*DIN) {
        int r = (k - DIN) / DIN, kk = (k - DIN) - r*DIN;
        v = wr[(size_t)(r*DIN + kk)*DOUT + n];
    }
    int l = (n & 7)*4 + ((k & 7) >> 1);
    int rg = (k >> 3) & 1, hb = k & 1;
    bp[((size_t)(n >> 3)*(K5P/16) + (k >> 4))*128 + l*4 + rg*2 + hb] = __float2half_rn(v);
}

__global__ void prep_kernel(const float* ws0, const float* wr0,
                            const float* ws1, const float* wr1,
                            const float* ws2, const float* wr2,
                            __half* wt)
{
    int idx = blockIdx.x*256 + threadIdx.x;
    if (blockIdx.x == 0 && threadIdx.x < 96) ((float*)g_stats)[threadIdx.x] = 0.f;
    if (idx < 2048)             wt_pack<5,64,32>    (ws0, wr0, wt,          idx);
    else if (idx < 43008)       wt_pack<64,128,320> (ws1, wr1, wt + 2048,   idx - 2048);
    else if (idx < 206848)      wt_pack<128,256,640>(ws2, wr2, wt + 43008,  idx - 43008);
}

// ---------------- X build, block0 only (fp32 atom feats, no norm) ----------------
__global__ void __launch_bounds__(256) x_build0(
    const float* __restrict__ hin, const float* __restrict__ adj,
    __half* __restrict__ Xo)
{
    constexpr int DIN = 5, K5P = 32, MB = 8;
    __shared__ float h_s[MB*NA*DIN];
    __shared__ float adj_s[MB*NR*NA*NA];
    const int tid = threadIdx.x;
    const size_t mb = (size_t)blockIdx.x * MB;
    for (int i = tid; i < MB*NA*DIN; i += 256)
        h_s[i] = hin[mb*NA*DIN + i];
    for (int i = tid; i < MB*NR*NA*NA; i += 256)
        adj_s[i] = adj[mb*NR*NA*NA + i];
    __syncthreads();
    for (int i = tid; i < MB*NA*(K5P/2); i += 256){
        int row = i / (K5P/2), pp = i - row*(K5P/2);
        int m = row / NA, n = row - m*NA;
        float vv[2];
        #pragma unroll
        for (int t = 0; t < 2; t++){
            int col = pp*2 + t;
            float v = 0.f;
            if (col < DIN) v = h_s[row*DIN + col];
            else if (col < 5*DIN){
                int r = (col - DIN) / DIN, d = (col - DIN) - r*DIN;
                const float* ar = &adj_s[((m*NR + r)*NA + n)*NA];
                const float* hc = &h_s[m*NA*DIN + d];
                #pragma unroll
                for (int mm = 0; mm < NA; mm++) v = fmaf(ar[mm], hc[mm*DIN], v);
            }
            vv[t] = v;
        }
        *(__half2*)&Xo[mb*NA*K5P + (size_t)row*K5P + pp*2] = __floats2half2_rn(vv[0], vv[1]);
    }
}

// ---------------- X build (register-blocked, fp16 h_s, 5 CTAs/SM) ----------------
// task = (batch, relation, 3-row n-tile, 8-col group) -> acc[3][8]
template<int DIN, int SIN>
__global__ void __launch_bounds__(256,5) x_build_s(
    const __half* __restrict__ hin,   // [B,9,DIN]
    const float* __restrict__ adj,    // [B,4,9,9]
    const float* __restrict__ gamma, const float* __restrict__ beta,
    __half* __restrict__ Xo,          // [B*9, 5*DIN]
    float invp)
{
    constexpr int K5P = 5*DIN;
    constexpr int MB  = 8;
    constexpr int NCG = DIN/8;
    __shared__ __align__(16) __half h_s[MB*NA*DIN];   // fp16
    __shared__ float adj_s[MB*NR*81];
    __shared__ float nrm[32];
    const int tid = threadIdx.x;
    const size_t mb = (size_t)blockIdx.x * MB;
    if (tid < NA){
        float s = g_stats[SIN][0][tid], q = g_stats[SIN][1][tid];
        float mean = s*invp, var = q*invp - mean*mean;
        float a = rsqrtf(var + BN_EPS) * gamma[tid];
        nrm[tid] = a; nrm[16+tid] = beta[tid] - mean*a;
    }
    __syncthreads();

    // phase A: load h (int4), normalize+act, store h_s fp16 AND X[:,0:DIN] fp16
    const int4* hv = (const int4*)(hin + mb*NA*DIN);
    for (int i = tid; i < MB*NA*DIN/8; i += 256){
        int4 raw = hv[i];
        __half2 hh[4];
        *(int*)&hh[0] = raw.x; *(int*)&hh[1] = raw.y;
        *(int*)&hh[2] = raw.z; *(int*)&hh[3] = raw.w;
        int idx0 = i*8;
        int row = idx0 / DIN;
        int n = row % NA;
        float a = nrm[n], c = nrm[16+n];
        __half2 pk[4];
        #pragma unroll
        for (int q = 0; q < 4; q++){
            float2 f = __half22float2(hh[q]);
            float v0 = fmaf(f.x, a, c); v0 = v0 > 0.f ? v0 : LRS*v0;
            float v1 = fmaf(f.y, a, c); v1 = v1 > 0.f ? v1 : LRS*v1;
            pk[q] = __floats2half2_rn(v0, v1);
        }
        int4 st;
        st.x = *(int*)&pk[0]; st.y = *(int*)&pk[1];
        st.z = *(int*)&pk[2]; st.w = *(int*)&pk[3];
        *(int4*)&h_s[idx0] = st;
        int col0 = idx0 - row*DIN;
        *(int4*)&Xo[(mb*NA + row)*K5P + col0] = st;
    }
    for (int i = tid; i < MB*NR*81; i += 256)
        adj_s[i] = adj[mb*NR*81 + i];
    __syncthreads();

    // phase B: task = (b, r, nt, cg); 3 output rows x 8 cols each; fp32 accum
    for (int t = tid; t < MB*NR*3*NCG; t += 256){
        int cg = t % NCG, t2 = t / NCG;
        int nt = t2 % 3, br = t2 / 3;
        int r = br % NR, b = br / NR;
        const float* arow = &adj_s[(b*NR + r)*81 + nt*3*9];
        const __half* hb  = &h_s[b*NA*DIN + cg*8];
        float acc[3][8];
        #pragma unroll
        for (int nn = 0; nn < 3; nn++)
            #pragma unroll
            for (int j = 0; j < 8; j++) acc[nn][j] = 0.f;
        #pragma unroll
        for (int m = 0; m < 9; m++){
            int4 raw = *(const int4*)&hb[m*DIN];
            __half2 hh[4];
            *(int*)&hh[0] = raw.x; *(int*)&hh[1] = raw.y;
            *(int*)&hh[2] = raw.z; *(int*)&hh[3] = raw.w;
            float h8[8];
            #pragma unroll
            for (int q = 0; q < 4; q++){
                float2 f = __half22float2(hh[q]);
                h8[2*q] = f.x; h8[2*q+1] = f.y;
            }
            #pragma unroll
            for (int nn = 0; nn < 3; nn++){
                float a = arow[nn*9 + m];
                #pragma unroll
                for (int j = 0; j < 8; j++) acc[nn][j] = fmaf(a, h8[j], acc[nn][j]);
            }
        }
        size_t xb0 = (mb + b)*NA*K5P + (size_t)(nt*3)*K5P + DIN + r*DIN + cg*8;
        #pragma unroll
        for (int nn = 0; nn < 3; nn++){
            __half2 p0 = __floats2half2_rn(acc[nn][0], acc[nn][1]);
            __half2 p1 = __floats2half2_rn(acc[nn][2], acc[nn][3]);
            __half2 p2 = __floats2half2_rn(acc[nn][4], acc[nn][5]);
            __half2 p3 = __floats2half2_rn(acc[nn][6], acc[nn][7]);
            int4 st; st.x = *(int*)&p0; st.y = *(int*)&p1;
            st.z = *(int*)&p2; st.w = *(int*)&p3;
            *(int4*)&Xo[xb0 + (size_t)nn*K5P] = st;
        }
    }
}

// ---------------- fp16 mma.sync GEMM, NSTG-deep cp.async pipeline ----------------
template<int N, int NCH, int K5P, int MROWS, int SOUT, int MINCTA, int NSTG>
__global__ void __launch_bounds__(256, MINCTA) gemm_mma(
    const __half* __restrict__ X,
    const __half* __restrict__ Bp,
    const float* __restrict__ bias,
    __half* __restrict__ hout)
{
    constexpr int MT_W = MROWS/64;
    constexpr int NT   = N/16;
    constexpr int ASTR = 40;
    constexpr int ASZ  = MROWS*ASTR;
    constexpr int BSZ  = N*32;
    extern __shared__ __align__(16) __half smh[];
    __half* As = smh;                 // [NSTG][ASZ]
    __half* Bs = smh + NSTG*ASZ;      // [NSTG][BSZ]
    __shared__ float red[32];
    __shared__ float bias_s[N];

    const int tid = threadIdx.x, lane = tid & 31, wid = tid >> 5;
    const int warp_n = wid & 1, warp_m = wid >> 1;
    const int mBase = blockIdx.x * MROWS;

    if (tid < 32) red[tid] = 0.f;
    for (int i = tid; i < N; i += 256) bias_s[i] = bias[i];

    auto loadA = [&](int kc, int s){
        const __half* src = X + (size_t)mBase*K5P + kc*32;
        #pragma unroll
        for (int i = tid; i < MROWS*4; i += 256){
            int row = i >> 2, seg = i & 3;
            CPA16(s2u(As + s*ASZ + row*ASTR + seg*8), src + (size_t)row*K5P + seg*8);
        }
    };
    auto loadB = [&](int kc, int s){
        #pragma unroll
        for (int i = tid; i < N*4; i += 256){
            int n8 = i >> 5, rem = i & 31, ks = rem >> 4, q = rem & 15;
            const __half* src = Bp + ((size_t)n8*(K5P/16) + kc*2 + ks)*128 + q*8;
            CPA16(s2u(Bs + s*BSZ + (n8*2 + ks)*128 + q*8), src);
        }
    };

    // prologue: NSTG-1 uniform commits
    #pragma unroll
    for (int s = 0; s < NSTG-1; s++){
        if (s < NCH){ loadA(s, s); loadB(s, s); }
        CPA_COMMIT();
    }

    float cacc[MT_W][NT][4];
    #pragma unroll
    for (int mtw=0; mtw<MT_W; mtw++)
        #pragma unroll
        for (int j=0;j<NT;j++)
            #pragma unroll
            for (int q=0;q<4;q++) cacc[mtw][j][q] = 0.f;

    for (int kc = 0; kc < NCH; kc++){
        CPA_WAIT(NSTG-2);               // chunk kc resident
        __syncthreads();                // all warps past compute(kc-1); data visible
        {
            int ld = kc + NSTG - 1;     // refill slot (kc-1)%NSTG
            if (ld < NCH){ loadA(ld, ld % NSTG); loadB(ld, ld % NSTG); }
            CPA_COMMIT();
        }
        const int s = kc % NSTG;
        const uint32_t* Au = (const uint32_t*)(As + s*ASZ);
        const uint32_t* Bu = (const uint32_t*)(Bs + s*BSZ);
        #pragma unroll
        for (int ks = 0; ks < 2; ks++){
            uint32_t a[MT_W][4];
            #pragma unroll
            for (int mtw = 0; mtw < MT_W; mtw++){
                int r0 = (warp_m*MT_W + mtw)*16 + (lane >> 2);
                int kw = ks*8 + (lane & 3);
                a[mtw][0] = Au[r0*20 + kw];
                a[mtw][1] = Au[(r0+8)*20 + kw];
                a[mtw][2] = Au[r0*20 + kw + 4];
                a[mtw][3] = Au[(r0+8)*20 + kw + 4];
            }
            #pragma unroll
            for (int j = 0; j < NT; j++){
                int n8 = warp_n*NT + j;
                uint32_t b0 = Bu[(n8*2 + ks)*64 + lane*2];
                uint32_t b1 = Bu[(n8*2 + ks)*64 + lane*2 + 1];
                #pragma unroll
                for (int mtw = 0; mtw < MT_W; mtw++)
                    mma_f16(cacc[mtw][j][0], cacc[mtw][j][1],
                            cacc[mtw][j][2], cacc[mtw][j][3],
                            a[mtw][0], a[mtw][1], a[mtw][2], a[mtw][3],
                            b0, b1);
            }
        }
    }

    // epilogue: bias, fp16 store, BN stats
    #pragma unroll
    for (int mtw = 0; mtw < MT_W; mtw++){
        #pragma unroll
        for (int half = 0; half < 2; half++){
            int r0   = (warp_m*MT_W + mtw)*16 + (lane >> 2) + half*8;
            int grow = mBase + r0;
            int an   = grow % NA;
            float ssum = 0.f, qsum = 0.f;
            __half* op = &hout[(size_t)grow*N];
            #pragma unroll
            for (int j = 0; j < NT; j++){
                int col = warp_n*(N/2) + j*8 + (lane & 3)*2;
                float v0 = cacc[mtw][j][half*2+0] + bias_s[col];
                float v1 = cacc[mtw][j][half*2+1] + bias_s[col+1];
                *(__half2*)(op + col) = __floats2half2_rn(v0, v1);
                ssum += v0 + v1;
                qsum = fmaf(v0, v0, qsum); qsum = fmaf(v1, v1, qsum);
            }
            atomicAdd(&red[an],      ssum);
            atomicAdd(&red[16 + an], qsum);
        }
    }
    __syncthreads();
    if (tid < NA){
        atomicAdd(&g_stats[SOUT][0][tid], red[tid]);
        atomicAdd(&g_stats[SOUT][1][tid], red[16 + tid]);
    }
}

// ---------------- readout: BN + act + masked sum + FC (int4 loads) ------------
__global__ void __launch_bounds__(256) readout_kernel(
    const float* __restrict__ mask, const float* __restrict__ fcw,
    const float* __restrict__ fcb,  const float* __restrict__ gamma,
    const float* __restrict__ beta, float* __restrict__ out, float inv_count)
{
    __shared__ float a_s[NA], c_s[NA], fcs[256];
    int tid = threadIdx.x;
    if (tid < NA){
        float s = g_stats[2][0][tid], q = g_stats[2][1][tid];
        float mean = s*inv_count, var = q*inv_count - mean*mean;
        float a = rsqrtf(var + BN_EPS)*gamma[tid];
        a_s[tid] = a; c_s[tid] = beta[tid] - mean*a;
    }
    fcs[tid] = fcw[tid];
    __syncthreads();
    int lane = tid & 31, w = tid >> 5;
    int b = blockIdx.x*8 + w;
    int e0 = lane*8;
    float accv = 0.f;
    #pragma unroll
    for (int n = 0; n < NA; n++){
        float mk = mask[b*NA + n];
        const int4* hp = (const int4*)(g_h2 + ((size_t)b*NA + n)*256);
        int4 raw = hp[lane];
        float aa = a_s[n], cc = c_s[n];
        __half2 hh[4];
        *(int*)&hh[0] = raw.x; *(int*)&hh[1] = raw.y;
        *(int*)&hh[2] = raw.z; *(int*)&hh[3] = raw.w;
        #pragma unroll
        for (int q = 0; q < 4; q++){
            float2 f = __half22float2(hh[q]);
            float v0 = fmaf(f.x, aa, cc); v0 = v0 > 0.f ? v0 : LRS*v0;
            float v1 = fmaf(f.y, aa, cc); v1 = v1 > 0.f ? v1 : LRS*v1;
            accv = fmaf(v0*mk, fcs[e0 + 2*q],     accv);
            accv = fmaf(v1*mk, fcs[e0 + 2*q + 1], accv);
        }
    }
    #pragma unroll
    for (int o = 16; o > 0; o >>= 1) accv += __shfl_xor_sync(0xffffffffu, accv, o);
    if (lane == 0) out[b] = accv + fcb[0];
}

extern "C" void kernel_launch(void* const* d_in, const int* in_sizes, int n_in,
                              void* d_out, int out_size)
{
    const float* atom = (const float*)d_in[0];
    const float* adj  = (const float*)d_in[1];
    const float* mask = (const float*)d_in[2];
    const float* ws0=(const float*)d_in[3],  *wr0=(const float*)d_in[4],  *b0=(const float*)d_in[5],  *g0=(const float*)d_in[6],  *be0=(const float*)d_in[7];
    const float* ws1=(const float*)d_in[8],  *wr1=(const float*)d_in[9],  *b1=(const float*)d_in[10], *g1=(const float*)d_in[11], *be1=(const float*)d_in[12];
    const float* ws2=(const float*)d_in[13], *wr2=(const float*)d_in[14], *b2=(const float*)d_in[15], *g2=(const float*)d_in[16], *be2=(const float*)d_in[17];
    const float* fcw=(const float*)d_in[18], *fcb=(const float*)d_in[19];
    float* out = (float*)d_out;

    __half *h0,*h1,*h2,*xb,*wtb;
    cudaGetSymbolAddress((void**)&h0, g_h0);
    cudaGetSymbolAddress((void**)&h1, g_h1);
    cudaGetSymbolAddress((void**)&h2, g_h2);
    cudaGetSymbolAddress((void**)&xb, g_x);
    cudaGetSymbolAddress((void**)&wtb, g_wt);

    // dynamic smem: NSTG*(MROWS*40 + N*32) halves * 2 bytes  (R14 configs)
    const int sm0 = 2*(128*40 + 64*32)  * 2;   //  28672
    const int sm1 = 5*(128*40 + 128*32) * 2;   //  92160
    const int sm2 = 4*(64*40  + 256*32) * 2;   //  86016
    cudaFuncSetAttribute((const void*)gemm_mma<64,1,32,128,0,3,2>,
                         cudaFuncAttributeMaxDynamicSharedMemorySize, sm0);
    cudaFuncSetAttribute((const void*)gemm_mma<128,10,320,128,1,2,5>,
                         cudaFuncAttributeMaxDynamicSharedMemorySize, sm1);
    cudaFuncSetAttribute((const void*)gemm_mma<256,20,640,64,2,2,4>,
                         cudaFuncAttributeMaxDynamicSharedMemorySize, sm2);

    prep_kernel<<<808,256>>>(ws0, wr0, ws1, wr1, ws2, wr2, wtb);

    // block 0
    x_build0<<<BATCH/8,256>>>(atom, adj, xb);
    gemm_mma<64,1,32,128,0,3,2><<<MTOT/128,256,sm0>>>(xb, wtb, b0, h0);

    // block 1
    x_build_s<64,0><<<BATCH/8,256>>>(h0, adj, g0, be0, xb, 1.f/((float)BATCH*64.f));
    gemm_mma<128,10,320,128,1,2,5><<<MTOT/128,256,sm1>>>(xb, wtb + 2048, b1, h1);

    // block 2
    x_build_s<128,1><<<BATCH/8,256>>>(h1, adj, g1, be1, xb, 1.f/((float)BATCH*128.f));
    gemm_mma<256,20,640,64,2,2,4><<<MTOT/64,256,sm2>>>(xb, wtb + 43008, b2, h2);

    readout_kernel<<<BATCH/8,256>>>(mask, fcw, fcb, g2, be2, out,
                                    1.f/((float)BATCH*256.f));
}